// round 1
// baseline (speedup 1.0000x reference)
#include <cuda_runtime.h>
#include <math.h>

#define Bsz 4
#define Sq  1024
#define Fd  1024
#define Hh  16
#define Dd  64

// Scratch (device globals: allocation-free per harness rules)
__device__ float g_q[Bsz*Hh*Sq*Dd];   // [B,H,S,D], pre-scaled by 1/sqrt(D)
__device__ float g_k[Bsz*Hh*Sq*Dd];   // [B,H,S,D]
__device__ float g_v[Bsz*Hh*Sq*Dd];   // [B,H,S,D]
__device__ float g_y[Bsz*Sq*Hh*Dd];   // [B,S,H*D] row-major (GEMM-ready)

// ---------------------------------------------------------------------------
// Kernel 1: fused QKV projection GEMM.
// X[4096,1024] @ W[1024,1024] + bias, z selects (Wq,Wk,Wv).
// BM=128, BN=128, BK=16, 256 threads, 8x8 per-thread microtile.
// Epilogue permutes to [B,H,S,D]; Q additionally scaled by 0.125.
// ---------------------------------------------------------------------------
__global__ __launch_bounds__(256) void qkv_gemm(
    const float* __restrict__ X,
    const float* __restrict__ Wq, const float* __restrict__ bq,
    const float* __restrict__ Wk, const float* __restrict__ bk,
    const float* __restrict__ Wv, const float* __restrict__ bv)
{
    const int z = blockIdx.z;
    const float* __restrict__ W   = (z == 0) ? Wq : (z == 1) ? Wk : Wv;
    const float* __restrict__ bia = (z == 0) ? bq : (z == 1) ? bk : bv;
    float* __restrict__ out       = (z == 0) ? g_q : (z == 1) ? g_k : g_v;
    const float scale = (z == 0) ? 0.125f : 1.0f;

    __shared__ float As[16][132];   // [k][m], pad 132 -> conflict-free + float4-aligned
    __shared__ float Bs[16][128];   // [k][n]

    const int tid = threadIdx.x;
    const int tx = tid & 15;        // n subtile
    const int ty = tid >> 4;        // m subtile
    const int m0 = blockIdx.y * 128;
    const int n0 = blockIdx.x * 128;

    float acc[8][8];
#pragma unroll
    for (int i = 0; i < 8; i++)
#pragma unroll
        for (int j = 0; j < 8; j++) acc[i][j] = 0.0f;

    for (int k0 = 0; k0 < Fd; k0 += 16) {
        // Load A tile 128x16 (transposed into As[k][m])
#pragma unroll
        for (int it = 0; it < 2; it++) {
            int idx = tid + it * 256;          // 0..511
            int m  = idx >> 2;                  // 0..127
            int ks = (idx & 3) * 4;             // 0,4,8,12
            float4 a = *reinterpret_cast<const float4*>(
                &X[(size_t)(m0 + m) * Fd + k0 + ks]);
            As[ks + 0][m] = a.x; As[ks + 1][m] = a.y;
            As[ks + 2][m] = a.z; As[ks + 3][m] = a.w;
        }
        // Load B tile 16x128
#pragma unroll
        for (int it = 0; it < 2; it++) {
            int idx = tid + it * 256;          // 0..511
            int kk = idx >> 5;                  // 0..15
            int n4 = (idx & 31) * 4;
            *reinterpret_cast<float4*>(&Bs[kk][n4]) =
                *reinterpret_cast<const float4*>(&W[(size_t)(k0 + kk) * Fd + n0 + n4]);
        }
        __syncthreads();

#pragma unroll
        for (int kk = 0; kk < 16; kk++) {
            float a[8], b[8];
            float4 a0 = *reinterpret_cast<const float4*>(&As[kk][ty * 8]);
            float4 a1 = *reinterpret_cast<const float4*>(&As[kk][ty * 8 + 4]);
            float4 b0 = *reinterpret_cast<const float4*>(&Bs[kk][tx * 8]);
            float4 b1 = *reinterpret_cast<const float4*>(&Bs[kk][tx * 8 + 4]);
            a[0]=a0.x; a[1]=a0.y; a[2]=a0.z; a[3]=a0.w;
            a[4]=a1.x; a[5]=a1.y; a[6]=a1.z; a[7]=a1.w;
            b[0]=b0.x; b[1]=b0.y; b[2]=b0.z; b[3]=b0.w;
            b[4]=b1.x; b[5]=b1.y; b[6]=b1.z; b[7]=b1.w;
#pragma unroll
            for (int i = 0; i < 8; i++)
#pragma unroll
                for (int j = 0; j < 8; j++)
                    acc[i][j] += a[i] * b[j];
        }
        __syncthreads();
    }

    // Epilogue: bias, scale, permute to [B,H,S,D]
#pragma unroll
    for (int i = 0; i < 8; i++) {
        int m = m0 + ty * 8 + i;
        int bb = m >> 10;           // batch
        int ss = m & 1023;          // seq pos
#pragma unroll
        for (int j = 0; j < 8; j++) {
            int n = n0 + tx * 8 + j;
            int hh = n >> 6;
            int dd = n & 63;
            float v = (acc[i][j] + bia[n]) * scale;
            out[(size_t)(bb * Hh + hh) * (Sq * Dd) + ss * Dd + dd] = v;
        }
    }
}

// ---------------------------------------------------------------------------
// Kernel 2: attention with additive R and online softmax.
// One thread per query row: q[64] + acc[64] in registers.
// Block: 128 threads = 128 query rows; loop over 32-key tiles.
// R tile staged in SMEM (coalesced) and reused in-place as score scratch.
// ---------------------------------------------------------------------------
__global__ __launch_bounds__(128) void attn_kernel(const float* __restrict__ R)
{
    __shared__ float Kt[32][64];
    __shared__ float Vt[32][64];
    __shared__ float Rt[128][36];   // pad 36: float4-aligned rows

    const int tid = threadIdx.x;
    const int q0  = blockIdx.x * 128;
    const int bh  = blockIdx.y;          // b*H + h
    const int hh  = bh & (Hh - 1);
    const int bb  = bh >> 4;
    const int qrow = q0 + tid;

    // Load my Q row (pre-scaled) into registers
    float q[64];
    {
        const float4* qp = reinterpret_cast<const float4*>(
            &g_q[(size_t)(bh * Sq + qrow) * Dd]);
#pragma unroll
        for (int d4 = 0; d4 < 16; d4++) {
            float4 v = qp[d4];
            q[d4*4+0]=v.x; q[d4*4+1]=v.y; q[d4*4+2]=v.z; q[d4*4+3]=v.w;
        }
    }

    float acc[64];
#pragma unroll
    for (int d = 0; d < 64; d++) acc[d] = 0.0f;
    float m = -1e30f, l = 0.0f;

    const size_t kvbase = (size_t)bh * Sq * Dd;
    const size_t rbase  = (size_t)hh * Sq * Sq + (size_t)q0 * Sq;

    for (int k0 = 0; k0 < Sq; k0 += 32) {
        __syncthreads();   // previous tile fully consumed
        // Load K,V tiles: 32x64 each, float4 (4 per thread)
#pragma unroll
        for (int it = 0; it < 4; it++) {
            int idx = tid + it * 128;        // 0..511
            int j  = idx >> 4;
            int d4 = (idx & 15) * 4;
            *reinterpret_cast<float4*>(&Kt[j][d4]) =
                *reinterpret_cast<const float4*>(&g_k[kvbase + (size_t)(k0 + j) * Dd + d4]);
            *reinterpret_cast<float4*>(&Vt[j][d4]) =
                *reinterpret_cast<const float4*>(&g_v[kvbase + (size_t)(k0 + j) * Dd + d4]);
        }
        // Load R tile: 128 q-rows x 32 keys, float4 (8 per thread)
#pragma unroll
        for (int it = 0; it < 8; it++) {
            int idx = tid + it * 128;        // 0..1023
            int r  = idx >> 3;                // 0..127
            int c4 = (idx & 7) * 4;           // 0..28
            *reinterpret_cast<float4*>(&Rt[r][c4]) =
                *reinterpret_cast<const float4*>(&R[rbase + (size_t)r * Sq + k0 + c4]);
        }
        __syncthreads();

        // Phase A: scores for 32 keys, store back into my Rt row
        float tmax = -1e30f;
#pragma unroll 4
        for (int j = 0; j < 32; j++) {
            const float4* kp = reinterpret_cast<const float4*>(&Kt[j][0]);
            float s0 = 0.f, s1 = 0.f, s2 = 0.f, s3 = 0.f;
#pragma unroll
            for (int d4 = 0; d4 < 16; d4++) {
                float4 kv = kp[d4];
                s0 += q[d4*4+0] * kv.x;
                s1 += q[d4*4+1] * kv.y;
                s2 += q[d4*4+2] * kv.z;
                s3 += q[d4*4+3] * kv.w;
            }
            float s = (s0 + s1) + (s2 + s3) + Rt[tid][j];
            Rt[tid][j] = s;
            tmax = fmaxf(tmax, s);
        }

        // Online softmax rescale
        float m_new = fmaxf(m, tmax);
        float sc = __expf(m - m_new);
        l *= sc;
#pragma unroll
        for (int d = 0; d < 64; d++) acc[d] *= sc;

        // Phase C: accumulate p * V
#pragma unroll 2
        for (int j = 0; j < 32; j++) {
            float p = __expf(Rt[tid][j] - m_new);
            l += p;
            const float4* vp = reinterpret_cast<const float4*>(&Vt[j][0]);
#pragma unroll
            for (int d4 = 0; d4 < 16; d4++) {
                float4 vv = vp[d4];
                acc[d4*4+0] += p * vv.x;
                acc[d4*4+1] += p * vv.y;
                acc[d4*4+2] += p * vv.z;
                acc[d4*4+3] += p * vv.w;
            }
        }
        m = m_new;
    }

    // Normalize and write y[b, q, h*64 + d] (GEMM-ready row-major [4096,1024])
    float inv = 1.0f / l;
    float* outp = &g_y[(size_t)(bb * Sq + qrow) * (Hh * Dd) + hh * Dd];
#pragma unroll
    for (int d4 = 0; d4 < 16; d4++) {
        float4 v;
        v.x = acc[d4*4+0] * inv;
        v.y = acc[d4*4+1] * inv;
        v.z = acc[d4*4+2] * inv;
        v.w = acc[d4*4+3] * inv;
        *reinterpret_cast<float4*>(&outp[d4 * 4]) = v;
    }
}

// ---------------------------------------------------------------------------
// Kernel 3: output projection GEMM. y[4096,1024] @ Wo[1024,1024] + bo.
// Same tiling as kernel 1.
// ---------------------------------------------------------------------------
__global__ __launch_bounds__(256) void out_gemm(
    const float* __restrict__ Wo, const float* __restrict__ bo,
    float* __restrict__ out)
{
    __shared__ float As[16][132];
    __shared__ float Bs[16][128];

    const int tid = threadIdx.x;
    const int tx = tid & 15;
    const int ty = tid >> 4;
    const int m0 = blockIdx.y * 128;
    const int n0 = blockIdx.x * 128;

    float acc[8][8];
#pragma unroll
    for (int i = 0; i < 8; i++)
#pragma unroll
        for (int j = 0; j < 8; j++) acc[i][j] = 0.0f;

    for (int k0 = 0; k0 < Fd; k0 += 16) {
#pragma unroll
        for (int it = 0; it < 2; it++) {
            int idx = tid + it * 256;
            int mm = idx >> 2;
            int ks = (idx & 3) * 4;
            float4 a = *reinterpret_cast<const float4*>(
                &g_y[(size_t)(m0 + mm) * Fd + k0 + ks]);
            As[ks + 0][mm] = a.x; As[ks + 1][mm] = a.y;
            As[ks + 2][mm] = a.z; As[ks + 3][mm] = a.w;
        }
#pragma unroll
        for (int it = 0; it < 2; it++) {
            int idx = tid + it * 256;
            int kk = idx >> 5;
            int n4 = (idx & 31) * 4;
            *reinterpret_cast<float4*>(&Bs[kk][n4]) =
                *reinterpret_cast<const float4*>(&Wo[(size_t)(k0 + kk) * Fd + n0 + n4]);
        }
        __syncthreads();

#pragma unroll
        for (int kk = 0; kk < 16; kk++) {
            float a[8], b[8];
            float4 a0 = *reinterpret_cast<const float4*>(&As[kk][ty * 8]);
            float4 a1 = *reinterpret_cast<const float4*>(&As[kk][ty * 8 + 4]);
            float4 b0 = *reinterpret_cast<const float4*>(&Bs[kk][tx * 8]);
            float4 b1 = *reinterpret_cast<const float4*>(&Bs[kk][tx * 8 + 4]);
            a[0]=a0.x; a[1]=a0.y; a[2]=a0.z; a[3]=a0.w;
            a[4]=a1.x; a[5]=a1.y; a[6]=a1.z; a[7]=a1.w;
            b[0]=b0.x; b[1]=b0.y; b[2]=b0.z; b[3]=b0.w;
            b[4]=b1.x; b[5]=b1.y; b[6]=b1.z; b[7]=b1.w;
#pragma unroll
            for (int i = 0; i < 8; i++)
#pragma unroll
                for (int j = 0; j < 8; j++)
                    acc[i][j] += a[i] * b[j];
        }
        __syncthreads();
    }

#pragma unroll
    for (int i = 0; i < 8; i++) {
        int mm = m0 + ty * 8 + i;
#pragma unroll
        for (int j = 0; j < 8; j++) {
            int n = n0 + tx * 8 + j;
            out[(size_t)mm * Fd + n] = acc[i][j] + bo[n];
        }
    }
}

// ---------------------------------------------------------------------------
extern "C" void kernel_launch(void* const* d_in, const int* in_sizes, int n_in,
                              void* d_out, int out_size)
{
    const float* inputs_q = (const float*)d_in[0];
    const float* Wq = (const float*)d_in[1];
    const float* bq = (const float*)d_in[2];
    const float* Wk = (const float*)d_in[3];
    const float* bk = (const float*)d_in[4];
    const float* Wv = (const float*)d_in[5];
    const float* bv = (const float*)d_in[6];
    const float* R  = (const float*)d_in[7];
    const float* Wo = (const float*)d_in[8];
    const float* bo = (const float*)d_in[9];
    float* out = (float*)d_out;

    // 1) QKV projections: grid (N/128, M/128, 3)
    qkv_gemm<<<dim3(Fd / 128, (Bsz * Sq) / 128, 3), 256>>>(
        inputs_q, Wq, bq, Wk, bk, Wv, bv);

    // 2) Attention: grid (S/128 q-tiles, B*H)
    attn_kernel<<<dim3(Sq / 128, Bsz * Hh), 128>>>(R);

    // 3) Output projection
    out_gemm<<<dim3(Fd / 128, (Bsz * Sq) / 128), 256>>>(Wo, bo, out);
}

// round 3
// speedup vs baseline: 1.3922x; 1.3922x over previous
#include <cuda_runtime.h>
#include <cuda_bf16.h>
#include <math.h>
#include <stdint.h>

#define Bsz 4
#define Sq  1024
#define Fd  1024
#define Hh  16
#define Dd  64

// ---------------------------------------------------------------------------
// Scratch (device globals: allocation-free per harness rules)
// ---------------------------------------------------------------------------
__device__ float g_q[Bsz*Sq*Fd];   // [B,S,F]
__device__ float g_k[Bsz*Sq*Fd];
__device__ float g_v[Bsz*Sq*Fd];

__device__ __nv_bfloat16 g_xhi[Bsz*Sq*Fd];
__device__ __nv_bfloat16 g_xlo[Bsz*Sq*Fd];
// Transposed weights [N=1024][K=1024], 4 matrices: Wq, Wk, Wv, Wo
__device__ __nv_bfloat16 g_wthi[4*Fd*Fd];
__device__ __nv_bfloat16 g_wtlo[4*Fd*Fd];
// Attention output, bf16 hi/lo split, [B*S, F] row-major
__device__ __nv_bfloat16 g_yhi[Bsz*Sq*Fd];
__device__ __nv_bfloat16 g_ylo[Bsz*Sq*Fd];

// ---------------------------------------------------------------------------
// PTX helpers (baseline PTX only — no sm_103a-specific features)
// ---------------------------------------------------------------------------
__device__ __forceinline__ uint32_t smem_u32(const void* p) {
    uint32_t a;
    asm("{ .reg .u64 t; cvta.to.shared.u64 t, %1; cvt.u32.u64 %0, t; }"
        : "=r"(a) : "l"(p));
    return a;
}

#define CPA(dst, src) do {                                                   \
    uint64_t _g = __cvta_generic_to_global((const void*)(src));              \
    asm volatile("cp.async.ca.shared.global [%0], [%1], 16;"                 \
                 :: "r"(dst), "l"(_g) : "memory");                           \
} while (0)
#define CPC() asm volatile("cp.async.commit_group;" ::: "memory")
#define CPW() asm volatile("cp.async.wait_group 0;" ::: "memory")

__device__ __forceinline__ void ldsm4(uint32_t r[4], uint32_t addr) {
    asm volatile("ldmatrix.sync.aligned.m8n8.x4.shared.b16 {%0,%1,%2,%3}, [%4];"
        : "=r"(r[0]), "=r"(r[1]), "=r"(r[2]), "=r"(r[3]) : "r"(addr));
}

__device__ __forceinline__ void mma16816(float* c, const uint32_t* a,
                                         uint32_t b0, uint32_t b1) {
    asm volatile("mma.sync.aligned.m16n8k16.row.col.f32.bf16.bf16.f32 "
        "{%0,%1,%2,%3}, {%4,%5,%6,%7}, {%8,%9}, {%0,%1,%2,%3};"
        : "+f"(c[0]), "+f"(c[1]), "+f"(c[2]), "+f"(c[3])
        : "r"(a[0]), "r"(a[1]), "r"(a[2]), "r"(a[3]), "r"(b0), "r"(b1));
}

// ---------------------------------------------------------------------------
// Conversions
// ---------------------------------------------------------------------------
__global__ void split_x(const float* __restrict__ X) {
    int i = (blockIdx.x * blockDim.x + threadIdx.x) * 4;
    float4 v = *reinterpret_cast<const float4*>(&X[i]);
    float vv[4] = {v.x, v.y, v.z, v.w};
#pragma unroll
    for (int j = 0; j < 4; j++) {
        __nv_bfloat16 h = __float2bfloat16(vv[j]);
        g_xhi[i + j] = h;
        g_xlo[i + j] = __float2bfloat16(vv[j] - __bfloat162float(h));
    }
}

__global__ void split_wt(const float* __restrict__ Wq, const float* __restrict__ Wk,
                         const float* __restrict__ Wv, const float* __restrict__ Wo) {
    __shared__ float t[32][33];
    const int z = blockIdx.z;
    const float* __restrict__ W = (z == 0) ? Wq : (z == 1) ? Wk : (z == 2) ? Wv : Wo;
    __nv_bfloat16* hi = g_wthi + (size_t)z * Fd * Fd;
    __nv_bfloat16* lo = g_wtlo + (size_t)z * Fd * Fd;

    const int tx = threadIdx.x, ty = threadIdx.y;
    const int kbase = blockIdx.y * 32, nbase = blockIdx.x * 32;
#pragma unroll
    for (int i = 0; i < 4; i++) {
        int kr = ty * 4 + i;
        t[kr][tx] = W[(size_t)(kbase + kr) * Fd + nbase + tx];
    }
    __syncthreads();
#pragma unroll
    for (int i = 0; i < 4; i++) {
        int nr = ty * 4 + i;
        float v = t[tx][nr];
        __nv_bfloat16 h = __float2bfloat16(v);
        size_t o = (size_t)(nbase + nr) * Fd + kbase + tx;
        hi[o] = h;
        lo[o] = __float2bfloat16(v - __bfloat162float(h));
    }
}

// ---------------------------------------------------------------------------
// mma.sync GEMM: C[128x128 tile] += A[4096,1024] @ B^T[1024,1024]
// bf16 hi/lo 3-term split, fp32 accumulate, cp.async double buffer.
// 256 threads = 8 warps (2 M x 4 N), warp tile 64x32, BK=32.
// SMEM stage: Ahi(10240) Alo(10240) Bhi(10240) Blo(10240) = 40960; x2 = 81920.
// Row stride 80B (32 bf16 + 8 pad) -> conflict-free ldmatrix.
// ---------------------------------------------------------------------------
#define GSMEM 81920

__device__ __forceinline__ void gemm_mma(
    const __nv_bfloat16* __restrict__ Ahi, const __nv_bfloat16* __restrict__ Alo,
    const __nv_bfloat16* __restrict__ Bhi, const __nv_bfloat16* __restrict__ Blo,
    const float* __restrict__ bias, float* __restrict__ C, float scale,
    int m0, int n0)
{
    extern __shared__ __align__(128) char smem[];
    const uint32_t sb = smem_u32(smem);
    const int tid = threadIdx.x;
    const int lane = tid & 31, wid = tid >> 5;
    const int wm = (wid >> 2) * 64;   // 0 or 64
    const int wn = (wid & 3) * 32;    // 0,32,64,96

    float c[4][4][4];
#pragma unroll
    for (int i = 0; i < 4; i++)
#pragma unroll
        for (int j = 0; j < 4; j++)
#pragma unroll
            for (int r = 0; r < 4; r++) c[i][j][r] = 0.0f;

    const char* pAhi = (const char*)Ahi;
    const char* pAlo = (const char*)Alo;
    const char* pBhi = (const char*)Bhi;
    const char* pBlo = (const char*)Blo;

    auto load_stage = [&](int stg, int it) {
        const int k0 = it * 32;
        const uint32_t sbase = sb + stg * 40960;
#pragma unroll
        for (int t = 0; t < 2; t++) {
            int idx = tid + t * 256;
            int row = idx >> 2;
            int cc  = (idx & 3) * 8;
            uint32_t so = sbase + row * 80 + cc * 2;
            size_t goA = ((size_t)(m0 + row) * Fd + k0 + cc) * 2;
            size_t goB = ((size_t)(n0 + row) * Fd + k0 + cc) * 2;
            CPA(so +     0, pAhi + goA);
            CPA(so + 10240, pAlo + goA);
            CPA(so + 20480, pBhi + goB);
            CPA(so + 30720, pBlo + goB);
        }
        CPC();
    };

    const int g = lane >> 3, r8 = lane & 7;

    auto compute = [&](int stg) {
        const uint32_t abase = sb + stg * 40960;
        const uint32_t bbase = abase + 20480;
#pragma unroll
        for (int ks = 0; ks < 2; ks++) {
            uint32_t ah[16], al[16];
            const int arow = (g & 1) * 8 + r8;
            const int acol = ks * 16 + (g >> 1) * 8;
#pragma unroll
            for (int mi = 0; mi < 4; mi++) {
                uint32_t ad = abase + (uint32_t)((wm + mi * 16 + arow) * 80 + acol * 2);
                ldsm4(&ah[mi * 4], ad);
                ldsm4(&al[mi * 4], ad + 10240);
            }
#pragma unroll
            for (int j2 = 0; j2 < 2; j2++) {
                uint32_t bh[4], bl[4];
                const int brow = (2 * j2 + (g >> 1)) * 8 + r8;
                const int bcol = ks * 16 + (g & 1) * 8;
                uint32_t bd = bbase + (uint32_t)((wn + brow) * 80 + bcol * 2);
                ldsm4(bh, bd);
                ldsm4(bl, bd + 10240);
#pragma unroll
                for (int mi = 0; mi < 4; mi++) {
#pragma unroll
                    for (int jj = 0; jj < 2; jj++) {
                        const int nj = 2 * j2 + jj;
                        mma16816(c[mi][nj], &ah[mi * 4], bh[jj * 2], bh[jj * 2 + 1]);
                        mma16816(c[mi][nj], &ah[mi * 4], bl[jj * 2], bl[jj * 2 + 1]);
                        mma16816(c[mi][nj], &al[mi * 4], bh[jj * 2], bh[jj * 2 + 1]);
                    }
                }
            }
        }
    };

    load_stage(0, 0);
    CPW();
    __syncthreads();
    for (int it = 0; it < Fd / 32; it++) {
        if (it + 1 < Fd / 32) load_stage((it + 1) & 1, it + 1);
        compute(it & 1);
        if (it + 1 < Fd / 32) CPW();
        __syncthreads();
    }

    // Epilogue: bias + scale, float2 stores
    const int crow = lane >> 2;
    const int ccol = (lane & 3) * 2;
#pragma unroll
    for (int mi = 0; mi < 4; mi++) {
#pragma unroll
        for (int nj = 0; nj < 4; nj++) {
            const int m = m0 + wm + mi * 16 + crow;
            const int n = n0 + wn + nj * 8 + ccol;
            const float b0 = __ldg(&bias[n]);
            const float b1 = __ldg(&bias[n + 1]);
            float2 o0, o1;
            o0.x = (c[mi][nj][0] + b0) * scale;
            o0.y = (c[mi][nj][1] + b1) * scale;
            o1.x = (c[mi][nj][2] + b0) * scale;
            o1.y = (c[mi][nj][3] + b1) * scale;
            *reinterpret_cast<float2*>(&C[(size_t)m * Fd + n]) = o0;
            *reinterpret_cast<float2*>(&C[(size_t)(m + 8) * Fd + n]) = o1;
        }
    }
}

__global__ __launch_bounds__(256) void qkv_gemm(
    const float* __restrict__ bq, const float* __restrict__ bk,
    const float* __restrict__ bv)
{
    const int z = blockIdx.z;
    const float* bias = (z == 0) ? bq : (z == 1) ? bk : bv;
    float* C = (z == 0) ? g_q : (z == 1) ? g_k : g_v;
    const float scale = (z == 0) ? 0.125f : 1.0f;
    gemm_mma(g_xhi, g_xlo,
             g_wthi + (size_t)z * Fd * Fd, g_wtlo + (size_t)z * Fd * Fd,
             bias, C, scale, blockIdx.y * 128, blockIdx.x * 128);
}

__global__ __launch_bounds__(256) void out_gemm(
    const float* __restrict__ bo, float* __restrict__ out)
{
    gemm_mma(g_yhi, g_ylo,
             g_wthi + (size_t)3 * Fd * Fd, g_wtlo + (size_t)3 * Fd * Fd,
             bo, out, 1.0f, blockIdx.y * 128, blockIdx.x * 128);
}

// ---------------------------------------------------------------------------
// Attention: one thread per query row, online softmax, additive R.
// q/k/v in [B,S,F]. Output written bf16 hi/lo.
// ---------------------------------------------------------------------------
__global__ __launch_bounds__(128) void attn_kernel(const float* __restrict__ R)
{
    __shared__ float Kt[32][64];
    __shared__ float Vt[32][64];
    __shared__ float Rt[128][36];

    const int tid = threadIdx.x;
    const int q0  = blockIdx.x * 128;
    const int bh  = blockIdx.y;
    const int hh  = bh & (Hh - 1);
    const int bb  = bh >> 4;
    const int qrow = q0 + tid;

    float q[64];
    {
        const float4* qp = reinterpret_cast<const float4*>(
            &g_q[((size_t)(bb * Sq + qrow)) * Fd + hh * Dd]);
#pragma unroll
        for (int d4 = 0; d4 < 16; d4++) {
            float4 v = qp[d4];
            q[d4*4+0]=v.x; q[d4*4+1]=v.y; q[d4*4+2]=v.z; q[d4*4+3]=v.w;
        }
    }

    float acc[64];
#pragma unroll
    for (int d = 0; d < 64; d++) acc[d] = 0.0f;
    float m = -1e30f, l = 0.0f;

    const size_t rbase = (size_t)hh * Sq * Sq + (size_t)q0 * Sq;

    for (int k0 = 0; k0 < Sq; k0 += 32) {
        __syncthreads();
#pragma unroll
        for (int it = 0; it < 4; it++) {
            int idx = tid + it * 128;
            int j  = idx >> 4;
            int d4 = (idx & 15) * 4;
            size_t gb = ((size_t)(bb * Sq + k0 + j)) * Fd + hh * Dd + d4;
            *reinterpret_cast<float4*>(&Kt[j][d4]) =
                *reinterpret_cast<const float4*>(&g_k[gb]);
            *reinterpret_cast<float4*>(&Vt[j][d4]) =
                *reinterpret_cast<const float4*>(&g_v[gb]);
        }
#pragma unroll
        for (int it = 0; it < 8; it++) {
            int idx = tid + it * 128;
            int r  = idx >> 3;
            int c4 = (idx & 7) * 4;
            *reinterpret_cast<float4*>(&Rt[r][c4]) =
                *reinterpret_cast<const float4*>(&R[rbase + (size_t)r * Sq + k0 + c4]);
        }
        __syncthreads();

        float tmax = -1e30f;
#pragma unroll 4
        for (int j = 0; j < 32; j++) {
            const float4* kp = reinterpret_cast<const float4*>(&Kt[j][0]);
            float s0 = 0.f, s1 = 0.f, s2 = 0.f, s3 = 0.f;
#pragma unroll
            for (int d4 = 0; d4 < 16; d4++) {
                float4 kv = kp[d4];
                s0 += q[d4*4+0] * kv.x;
                s1 += q[d4*4+1] * kv.y;
                s2 += q[d4*4+2] * kv.z;
                s3 += q[d4*4+3] * kv.w;
            }
            float s = (s0 + s1) + (s2 + s3) + Rt[tid][j];
            Rt[tid][j] = s;
            tmax = fmaxf(tmax, s);
        }

        float m_new = fmaxf(m, tmax);
        float sc = __expf(m - m_new);
        l *= sc;
#pragma unroll
        for (int d = 0; d < 64; d++) acc[d] *= sc;

#pragma unroll 2
        for (int j = 0; j < 32; j++) {
            float p = __expf(Rt[tid][j] - m_new);
            l += p;
            const float4* vp = reinterpret_cast<const float4*>(&Vt[j][0]);
#pragma unroll
            for (int d4 = 0; d4 < 16; d4++) {
                float4 vv = vp[d4];
                acc[d4*4+0] += p * vv.x;
                acc[d4*4+1] += p * vv.y;
                acc[d4*4+2] += p * vv.z;
                acc[d4*4+3] += p * vv.w;
            }
        }
        m = m_new;
    }

    float inv = 1.0f / l;
    size_t obase = ((size_t)(bb * Sq + qrow)) * Fd + hh * Dd;
    uint32_t* ph = reinterpret_cast<uint32_t*>(&g_yhi[obase]);
    uint32_t* pl = reinterpret_cast<uint32_t*>(&g_ylo[obase]);
#pragma unroll
    for (int d2 = 0; d2 < 32; d2++) {
        float o0 = acc[2*d2]   * inv;
        float o1 = acc[2*d2+1] * inv;
        __nv_bfloat16 h0 = __float2bfloat16(o0);
        __nv_bfloat16 h1 = __float2bfloat16(o1);
        __nv_bfloat16 l0 = __float2bfloat16(o0 - __bfloat162float(h0));
        __nv_bfloat16 l1 = __float2bfloat16(o1 - __bfloat162float(h1));
        __nv_bfloat162 hp = __nv_bfloat162(h0, h1);
        __nv_bfloat162 lp = __nv_bfloat162(l0, l1);
        ph[d2] = *reinterpret_cast<uint32_t*>(&hp);
        pl[d2] = *reinterpret_cast<uint32_t*>(&lp);
    }
}

// ---------------------------------------------------------------------------
extern "C" void kernel_launch(void* const* d_in, const int* in_sizes, int n_in,
                              void* d_out, int out_size)
{
    const float* inputs_q = (const float*)d_in[0];
    const float* Wq = (const float*)d_in[1];
    const float* bq = (const float*)d_in[2];
    const float* Wk = (const float*)d_in[3];
    const float* bk = (const float*)d_in[4];
    const float* Wv = (const float*)d_in[5];
    const float* bv = (const float*)d_in[6];
    const float* R  = (const float*)d_in[7];
    const float* Wo = (const float*)d_in[8];
    const float* bo = (const float*)d_in[9];
    float* out = (float*)d_out;

    cudaFuncSetAttribute(qkv_gemm, cudaFuncAttributeMaxDynamicSharedMemorySize, GSMEM);
    cudaFuncSetAttribute(out_gemm, cudaFuncAttributeMaxDynamicSharedMemorySize, GSMEM);

    split_x<<<4096, 256>>>(inputs_q);
    split_wt<<<dim3(32, 32, 4), dim3(32, 8)>>>(Wq, Wk, Wv, Wo);

    qkv_gemm<<<dim3(Fd / 128, (Bsz * Sq) / 128, 3), 256, GSMEM>>>(bq, bk, bv);

    attn_kernel<<<dim3(Sq / 128, Bsz * Hh), 128>>>(R);

    out_gemm<<<dim3(Fd / 128, (Bsz * Sq) / 128), 256, GSMEM>>>(bo, out);
}

// round 4
// speedup vs baseline: 2.5826x; 1.8551x over previous
#include <cuda_runtime.h>
#include <cuda_bf16.h>
#include <math.h>
#include <stdint.h>

#define Bsz 4
#define Sq  1024
#define Fd  1024
#define Hh  16
#define Dd  64

// ---------------------------------------------------------------------------
// Scratch (device globals)
// ---------------------------------------------------------------------------
__device__ __nv_bfloat16 g_xhi[Bsz*Sq*Fd];
__device__ __nv_bfloat16 g_xlo[Bsz*Sq*Fd];
__device__ __nv_bfloat16 g_wthi[4*Fd*Fd];   // [N][K] x4 (Wq,Wk,Wv,Wo)
__device__ __nv_bfloat16 g_wtlo[4*Fd*Fd];
// Q/K/V bf16 hi/lo in [B*H][S][D]
__device__ __nv_bfloat16 g_qh[Bsz*Hh*Sq*Dd];
__device__ __nv_bfloat16 g_ql[Bsz*Hh*Sq*Dd];
__device__ __nv_bfloat16 g_kh[Bsz*Hh*Sq*Dd];
__device__ __nv_bfloat16 g_kl[Bsz*Hh*Sq*Dd];
__device__ __nv_bfloat16 g_vh[Bsz*Hh*Sq*Dd];
__device__ __nv_bfloat16 g_vl[Bsz*Hh*Sq*Dd];
// Attention output bf16 hi/lo, [B*S][F]
__device__ __nv_bfloat16 g_yhi[Bsz*Sq*Fd];
__device__ __nv_bfloat16 g_ylo[Bsz*Sq*Fd];

// ---------------------------------------------------------------------------
// PTX helpers (baseline PTX only)
// ---------------------------------------------------------------------------
__device__ __forceinline__ uint32_t smem_u32(const void* p) {
    uint32_t a;
    asm("{ .reg .u64 t; cvta.to.shared.u64 t, %1; cvt.u32.u64 %0, t; }"
        : "=r"(a) : "l"(p));
    return a;
}

#define CPA(dst, src) do {                                                   \
    uint64_t _g = __cvta_generic_to_global((const void*)(src));              \
    asm volatile("cp.async.ca.shared.global [%0], [%1], 16;"                 \
                 :: "r"(dst), "l"(_g) : "memory");                           \
} while (0)
#define CPC() asm volatile("cp.async.commit_group;" ::: "memory")
#define CPW() asm volatile("cp.async.wait_group 0;" ::: "memory")

__device__ __forceinline__ void ldsm4(uint32_t r[4], uint32_t addr) {
    asm volatile("ldmatrix.sync.aligned.m8n8.x4.shared.b16 {%0,%1,%2,%3}, [%4];"
        : "=r"(r[0]), "=r"(r[1]), "=r"(r[2]), "=r"(r[3]) : "r"(addr));
}
__device__ __forceinline__ void ldsm4t(uint32_t r[4], uint32_t addr) {
    asm volatile("ldmatrix.sync.aligned.m8n8.x4.trans.shared.b16 {%0,%1,%2,%3}, [%4];"
        : "=r"(r[0]), "=r"(r[1]), "=r"(r[2]), "=r"(r[3]) : "r"(addr));
}

__device__ __forceinline__ void mma16816(float* c, const uint32_t* a,
                                         uint32_t b0, uint32_t b1) {
    asm volatile("mma.sync.aligned.m16n8k16.row.col.f32.bf16.bf16.f32 "
        "{%0,%1,%2,%3}, {%4,%5,%6,%7}, {%8,%9}, {%0,%1,%2,%3};"
        : "+f"(c[0]), "+f"(c[1]), "+f"(c[2]), "+f"(c[3])
        : "r"(a[0]), "r"(a[1]), "r"(a[2]), "r"(a[3]), "r"(b0), "r"(b1));
}

__device__ __forceinline__ uint32_t packbf2(float lo, float hi) {
    __nv_bfloat162 p = __nv_bfloat162(__float2bfloat16(lo), __float2bfloat16(hi));
    return *reinterpret_cast<uint32_t*>(&p);
}

// ---------------------------------------------------------------------------
// Conversions
// ---------------------------------------------------------------------------
__global__ void split_x(const float* __restrict__ X) {
    int i = (blockIdx.x * blockDim.x + threadIdx.x) * 4;
    float4 v = *reinterpret_cast<const float4*>(&X[i]);
    float vv[4] = {v.x, v.y, v.z, v.w};
#pragma unroll
    for (int j = 0; j < 4; j++) {
        __nv_bfloat16 h = __float2bfloat16(vv[j]);
        g_xhi[i + j] = h;
        g_xlo[i + j] = __float2bfloat16(vv[j] - __bfloat162float(h));
    }
}

__global__ void split_wt(const float* __restrict__ Wq, const float* __restrict__ Wk,
                         const float* __restrict__ Wv, const float* __restrict__ Wo) {
    __shared__ float t[32][33];
    const int z = blockIdx.z;
    const float* __restrict__ W = (z == 0) ? Wq : (z == 1) ? Wk : (z == 2) ? Wv : Wo;
    __nv_bfloat16* hi = g_wthi + (size_t)z * Fd * Fd;
    __nv_bfloat16* lo = g_wtlo + (size_t)z * Fd * Fd;

    const int tx = threadIdx.x, ty = threadIdx.y;
    const int kbase = blockIdx.y * 32, nbase = blockIdx.x * 32;
#pragma unroll
    for (int i = 0; i < 4; i++) {
        int kr = ty * 4 + i;
        t[kr][tx] = W[(size_t)(kbase + kr) * Fd + nbase + tx];
    }
    __syncthreads();
#pragma unroll
    for (int i = 0; i < 4; i++) {
        int nr = ty * 4 + i;
        float v = t[tx][nr];
        __nv_bfloat16 h = __float2bfloat16(v);
        size_t o = (size_t)(nbase + nr) * Fd + kbase + tx;
        hi[o] = h;
        lo[o] = __float2bfloat16(v - __bfloat162float(h));
    }
}

// ---------------------------------------------------------------------------
// mma.sync GEMM (same core as R3). MODE 0: fp32 C out. MODE 1: hi/lo bf16
// out in [B*H][S][D] layout (for Q/K/V).
// ---------------------------------------------------------------------------
#define GSMEM 81920

template<int MODE>
__device__ __forceinline__ void gemm_mma(
    const __nv_bfloat16* __restrict__ Ahi, const __nv_bfloat16* __restrict__ Alo,
    const __nv_bfloat16* __restrict__ Bhi, const __nv_bfloat16* __restrict__ Blo,
    const float* __restrict__ bias, float scale,
    float* __restrict__ C, __nv_bfloat16* __restrict__ Chi,
    __nv_bfloat16* __restrict__ Clo,
    int m0, int n0)
{
    extern __shared__ __align__(128) char smem[];
    const uint32_t sb = smem_u32(smem);
    const int tid = threadIdx.x;
    const int lane = tid & 31, wid = tid >> 5;
    const int wm = (wid >> 2) * 64;
    const int wn = (wid & 3) * 32;

    float c[4][4][4];
#pragma unroll
    for (int i = 0; i < 4; i++)
#pragma unroll
        for (int j = 0; j < 4; j++)
#pragma unroll
            for (int r = 0; r < 4; r++) c[i][j][r] = 0.0f;

    const char* pAhi = (const char*)Ahi;
    const char* pAlo = (const char*)Alo;
    const char* pBhi = (const char*)Bhi;
    const char* pBlo = (const char*)Blo;

    auto load_stage = [&](int stg, int it) {
        const int k0 = it * 32;
        const uint32_t sbase = sb + stg * 40960;
#pragma unroll
        for (int t = 0; t < 2; t++) {
            int idx = tid + t * 256;
            int row = idx >> 2;
            int cc  = (idx & 3) * 8;
            uint32_t so = sbase + row * 80 + cc * 2;
            size_t goA = ((size_t)(m0 + row) * Fd + k0 + cc) * 2;
            size_t goB = ((size_t)(n0 + row) * Fd + k0 + cc) * 2;
            CPA(so +     0, pAhi + goA);
            CPA(so + 10240, pAlo + goA);
            CPA(so + 20480, pBhi + goB);
            CPA(so + 30720, pBlo + goB);
        }
        CPC();
    };

    const int g = lane >> 3, r8 = lane & 7;

    auto compute = [&](int stg) {
        const uint32_t abase = sb + stg * 40960;
        const uint32_t bbase = abase + 20480;
#pragma unroll
        for (int ks = 0; ks < 2; ks++) {
            uint32_t ah[16], al[16];
            const int arow = (g & 1) * 8 + r8;
            const int acol = ks * 16 + (g >> 1) * 8;
#pragma unroll
            for (int mi = 0; mi < 4; mi++) {
                uint32_t ad = abase + (uint32_t)((wm + mi * 16 + arow) * 80 + acol * 2);
                ldsm4(&ah[mi * 4], ad);
                ldsm4(&al[mi * 4], ad + 10240);
            }
#pragma unroll
            for (int j2 = 0; j2 < 2; j2++) {
                uint32_t bh[4], bl[4];
                const int brow = (2 * j2 + (g >> 1)) * 8 + r8;
                const int bcol = ks * 16 + (g & 1) * 8;
                uint32_t bd = bbase + (uint32_t)((wn + brow) * 80 + bcol * 2);
                ldsm4(bh, bd);
                ldsm4(bl, bd + 10240);
#pragma unroll
                for (int mi = 0; mi < 4; mi++) {
#pragma unroll
                    for (int jj = 0; jj < 2; jj++) {
                        const int nj = 2 * j2 + jj;
                        mma16816(c[mi][nj], &ah[mi * 4], bh[jj * 2], bh[jj * 2 + 1]);
                        mma16816(c[mi][nj], &ah[mi * 4], bl[jj * 2], bl[jj * 2 + 1]);
                        mma16816(c[mi][nj], &al[mi * 4], bh[jj * 2], bh[jj * 2 + 1]);
                    }
                }
            }
        }
    };

    load_stage(0, 0);
    CPW();
    __syncthreads();
    for (int it = 0; it < Fd / 32; it++) {
        if (it + 1 < Fd / 32) load_stage((it + 1) & 1, it + 1);
        compute(it & 1);
        if (it + 1 < Fd / 32) CPW();
        __syncthreads();
    }

    const int crow = lane >> 2;
    const int ccol = (lane & 3) * 2;
#pragma unroll
    for (int mi = 0; mi < 4; mi++) {
#pragma unroll
        for (int nj = 0; nj < 4; nj++) {
            const int m = m0 + wm + mi * 16 + crow;
            const int n = n0 + wn + nj * 8 + ccol;
            const float b0 = __ldg(&bias[n]);
            const float b1 = __ldg(&bias[n + 1]);
            float v00 = (c[mi][nj][0] + b0) * scale;
            float v01 = (c[mi][nj][1] + b1) * scale;
            float v10 = (c[mi][nj][2] + b0) * scale;
            float v11 = (c[mi][nj][3] + b1) * scale;
            if (MODE == 0) {
                float2 o0 = {v00, v01}, o1 = {v10, v11};
                *reinterpret_cast<float2*>(&C[(size_t)m * Fd + n]) = o0;
                *reinterpret_cast<float2*>(&C[(size_t)(m + 8) * Fd + n]) = o1;
            } else {
                const int bb = m >> 10, ss = m & 1023;
                const int hh = n >> 6, dd = n & 63;
                size_t off0 = (((size_t)(bb * Hh + hh)) * Sq + ss) * Dd + dd;
                size_t off1 = off0 + 8 * Dd;
                __nv_bfloat16 h00 = __float2bfloat16(v00);
                __nv_bfloat16 h01 = __float2bfloat16(v01);
                __nv_bfloat16 h10 = __float2bfloat16(v10);
                __nv_bfloat16 h11 = __float2bfloat16(v11);
                __nv_bfloat162 hp0 = __nv_bfloat162(h00, h01);
                __nv_bfloat162 hp1 = __nv_bfloat162(h10, h11);
                __nv_bfloat162 lp0 = __nv_bfloat162(
                    __float2bfloat16(v00 - __bfloat162float(h00)),
                    __float2bfloat16(v01 - __bfloat162float(h01)));
                __nv_bfloat162 lp1 = __nv_bfloat162(
                    __float2bfloat16(v10 - __bfloat162float(h10)),
                    __float2bfloat16(v11 - __bfloat162float(h11)));
                *reinterpret_cast<uint32_t*>(&Chi[off0]) = *reinterpret_cast<uint32_t*>(&hp0);
                *reinterpret_cast<uint32_t*>(&Chi[off1]) = *reinterpret_cast<uint32_t*>(&hp1);
                *reinterpret_cast<uint32_t*>(&Clo[off0]) = *reinterpret_cast<uint32_t*>(&lp0);
                *reinterpret_cast<uint32_t*>(&Clo[off1]) = *reinterpret_cast<uint32_t*>(&lp1);
            }
        }
    }
}

__global__ __launch_bounds__(256) void qkv_gemm(
    const float* __restrict__ bq, const float* __restrict__ bk,
    const float* __restrict__ bv)
{
    const int z = blockIdx.z;
    const float* bias = (z == 0) ? bq : (z == 1) ? bk : bv;
    __nv_bfloat16* Chi = (z == 0) ? g_qh : (z == 1) ? g_kh : g_vh;
    __nv_bfloat16* Clo = (z == 0) ? g_ql : (z == 1) ? g_kl : g_vl;
    const float scale = (z == 0) ? 0.125f : 1.0f;
    gemm_mma<1>(g_xhi, g_xlo,
                g_wthi + (size_t)z * Fd * Fd, g_wtlo + (size_t)z * Fd * Fd,
                bias, scale, nullptr, Chi, Clo,
                blockIdx.y * 128, blockIdx.x * 128);
}

__global__ __launch_bounds__(256) void out_gemm(
    const float* __restrict__ bo, float* __restrict__ out)
{
    gemm_mma<0>(g_yhi, g_ylo,
                g_wthi + (size_t)3 * Fd * Fd, g_wtlo + (size_t)3 * Fd * Fd,
                bo, 1.0f, out, nullptr, nullptr,
                blockIdx.y * 128, blockIdx.x * 128);
}

// ---------------------------------------------------------------------------
// Flash attention with mma.sync, hi/lo split QK^T and PV, additive R.
// CTA: 64 q-rows x one (b,h); 4 warps (m16 each); key tiles of 64.
// ---------------------------------------------------------------------------
// smem per stage: KH 9216 | KL 9216 | VH 9216 | VL 9216 | R 17408 = 54272
#define AKH 0
#define AKL 9216
#define AVH 18432
#define AVL 27648
#define ARR 36864
#define ASTG 54272
#define ASMEM (2*ASTG)
#define KVPITCH 144
#define RPITCH 272

__global__ __launch_bounds__(128) void attn_mma(const float* __restrict__ R)
{
    extern __shared__ __align__(128) char smem[];
    const uint32_t sb = smem_u32(smem);
    const int tid = threadIdx.x;
    const int lane = tid & 31, w = tid >> 5;
    const int bb = blockIdx.x;
    const int hh = blockIdx.y >> 4;
    const int qt = blockIdx.y & 15;
    const int bh = bb * Hh + hh;

    const int lr = lane & 7;
    const int sel8  = (lane & 8) ? 8 : 0;
    const int sel16 = (lane & 16) ? 8 : 0;
    const int crow = lane >> 2;          // c-frag row within 16
    const int ct = (lane & 3) * 2;       // c-frag col pair

    const __nv_bfloat16* Kh = g_kh + (size_t)bh * Sq * Dd;
    const __nv_bfloat16* Kl = g_kl + (size_t)bh * Sq * Dd;
    const __nv_bfloat16* Vh = g_vh + (size_t)bh * Sq * Dd;
    const __nv_bfloat16* Vl = g_vl + (size_t)bh * Sq * Dd;
    const float* Rp = R + (size_t)hh * Sq * Sq + (size_t)(qt * 64) * Sq;

    auto load_stage = [&](int stg, int kt) {
        const int k0 = kt * 64;
        const uint32_t sbase = sb + stg * ASTG;
#pragma unroll
        for (int i = 0; i < 4; i++) {
            int idx = tid + i * 128;          // 0..511
            int row = idx >> 3;
            int seg = (idx & 7) * 16;         // byte offset in 128B row
            uint32_t so = sbase + row * KVPITCH + seg;
            size_t go = ((size_t)(k0 + row)) * Dd + (seg >> 1);   // bf16 elems
            CPA(so + AKH, Kh + go);
            CPA(so + AKL, Kl + go);
            CPA(so + AVH, Vh + go);
            CPA(so + AVL, Vl + go);
        }
#pragma unroll
        for (int i = 0; i < 8; i++) {
            int idx = tid + i * 128;          // 0..1023
            int row = idx >> 4;
            int seg = (idx & 15) * 16;        // byte offset in 256B row
            CPA(sbase + ARR + row * RPITCH + seg,
                Rp + (size_t)row * Sq + k0 + (seg >> 2));
        }
        CPC();
    };

    // ---- Load Q fragments (via stage-1 KH/KL area) ----
    load_stage(0, 0);
    {
        const uint32_t qbase = sb + ASTG;     // stage1 KH/KL
        const __nv_bfloat16* Qh = g_qh + ((size_t)bh * Sq + qt * 64) * Dd;
        const __nv_bfloat16* Ql = g_ql + ((size_t)bh * Sq + qt * 64) * Dd;
#pragma unroll
        for (int i = 0; i < 4; i++) {
            int idx = tid + i * 128;
            int row = idx >> 3;
            int seg = (idx & 7) * 16;
            uint32_t so = qbase + row * KVPITCH + seg;
            size_t go = (size_t)row * Dd + (seg >> 1);
            CPA(so + AKH, Qh + go);
            CPA(so + AKL, Ql + go);
        }
        CPC();
    }
    CPW();
    __syncthreads();

    uint32_t qfh[4][4], qfl[4][4];
    {
        const uint32_t qbase = sb + ASTG;
        const int arow = w * 16 + lr + sel8;
#pragma unroll
        for (int cc = 0; cc < 4; cc++) {
            const int acol = cc * 16 + sel16;
            uint32_t ad = qbase + (uint32_t)(arow * KVPITCH + acol * 2);
            ldsm4(qfh[cc], ad + AKH);
            ldsm4(qfl[cc], ad + AKL);
        }
    }
    __syncthreads();

    float o[8][4];
#pragma unroll
    for (int j = 0; j < 8; j++)
#pragma unroll
        for (int r = 0; r < 4; r++) o[j][r] = 0.0f;
    float mval0 = -1e30f, mval1 = -1e30f, lval0 = 0.0f, lval1 = 0.0f;

    for (int kt = 0; kt < 16; kt++) {
        if (kt + 1 < 16) load_stage((kt + 1) & 1, kt + 1);
        const uint32_t stg = sb + (kt & 1) * ASTG;

        // ---- QK^T (3-term hi/lo) ----
        float c[8][4];
#pragma unroll
        for (int j = 0; j < 8; j++)
#pragma unroll
            for (int r = 0; r < 4; r++) c[j][r] = 0.0f;

#pragma unroll
        for (int np = 0; np < 4; np++) {
            const int brow = np * 16 + lr + sel16;
#pragma unroll
            for (int cc = 0; cc < 4; cc++) {
                const int bcol = cc * 16 + sel8;
                uint32_t kd = stg + (uint32_t)(brow * KVPITCH + bcol * 2);
                uint32_t kh[4], kl[4];
                ldsm4(kh, kd + AKH);
                ldsm4(kl, kd + AKL);
                mma16816(c[2*np],   qfh[cc], kh[0], kh[1]);
                mma16816(c[2*np],   qfh[cc], kl[0], kl[1]);
                mma16816(c[2*np],   qfl[cc], kh[0], kh[1]);
                mma16816(c[2*np+1], qfh[cc], kh[2], kh[3]);
                mma16816(c[2*np+1], qfh[cc], kl[2], kl[3]);
                mma16816(c[2*np+1], qfl[cc], kh[2], kh[3]);
            }
        }

        // ---- add R, row max ----
        const char* rbase = smem + (kt & 1) * ASTG + ARR;
        const int rrow0 = w * 16 + crow;
        float mx0 = -1e30f, mx1 = -1e30f;
#pragma unroll
        for (int j = 0; j < 8; j++) {
            const int cj = j * 8 + ct;
            float2 r0 = *reinterpret_cast<const float2*>(rbase + rrow0 * RPITCH + cj * 4);
            float2 r1 = *reinterpret_cast<const float2*>(rbase + (rrow0 + 8) * RPITCH + cj * 4);
            c[j][0] += r0.x; c[j][1] += r0.y;
            c[j][2] += r1.x; c[j][3] += r1.y;
            mx0 = fmaxf(mx0, fmaxf(c[j][0], c[j][1]));
            mx1 = fmaxf(mx1, fmaxf(c[j][2], c[j][3]));
        }
        mx0 = fmaxf(mx0, __shfl_xor_sync(0xffffffffu, mx0, 1));
        mx0 = fmaxf(mx0, __shfl_xor_sync(0xffffffffu, mx0, 2));
        mx1 = fmaxf(mx1, __shfl_xor_sync(0xffffffffu, mx1, 1));
        mx1 = fmaxf(mx1, __shfl_xor_sync(0xffffffffu, mx1, 2));

        const float mn0 = fmaxf(mval0, mx0);
        const float mn1 = fmaxf(mval1, mx1);
        const float sc0 = __expf(mval0 - mn0);
        const float sc1 = __expf(mval1 - mn1);
        mval0 = mn0; mval1 = mn1;

        // ---- exp, split P into hi/lo A-fragments ----
        uint32_t pah[4][4], pal[4][4];
        float ls0 = 0.0f, ls1 = 0.0f;
#pragma unroll
        for (int j = 0; j < 8; j++) {
            float p00 = __expf(c[j][0] - mn0);
            float p01 = __expf(c[j][1] - mn0);
            float p10 = __expf(c[j][2] - mn1);
            float p11 = __expf(c[j][3] - mn1);
            ls0 += p00 + p01; ls1 += p10 + p11;
            __nv_bfloat16 h00 = __float2bfloat16(p00);
            __nv_bfloat16 h01 = __float2bfloat16(p01);
            __nv_bfloat16 h10 = __float2bfloat16(p10);
            __nv_bfloat16 h11 = __float2bfloat16(p11);
            const int kc = j >> 1, sl = (j & 1) * 2;
            {
                __nv_bfloat162 t0 = __nv_bfloat162(h00, h01);
                __nv_bfloat162 t1 = __nv_bfloat162(h10, h11);
                pah[kc][sl]   = *reinterpret_cast<uint32_t*>(&t0);
                pah[kc][sl+1] = *reinterpret_cast<uint32_t*>(&t1);
            }
            {
                __nv_bfloat162 t0 = __nv_bfloat162(
                    __float2bfloat16(p00 - __bfloat162float(h00)),
                    __float2bfloat16(p01 - __bfloat162float(h01)));
                __nv_bfloat162 t1 = __nv_bfloat162(
                    __float2bfloat16(p10 - __bfloat162float(h10)),
                    __float2bfloat16(p11 - __bfloat162float(h11)));
                pal[kc][sl]   = *reinterpret_cast<uint32_t*>(&t0);
                pal[kc][sl+1] = *reinterpret_cast<uint32_t*>(&t1);
            }
        }
        ls0 += __shfl_xor_sync(0xffffffffu, ls0, 1);
        ls0 += __shfl_xor_sync(0xffffffffu, ls0, 2);
        ls1 += __shfl_xor_sync(0xffffffffu, ls1, 1);
        ls1 += __shfl_xor_sync(0xffffffffu, ls1, 2);
        lval0 = lval0 * sc0 + ls0;
        lval1 = lval1 * sc1 + ls1;

        // ---- rescale O ----
#pragma unroll
        for (int j = 0; j < 8; j++) {
            o[j][0] *= sc0; o[j][1] *= sc0;
            o[j][2] *= sc1; o[j][3] *= sc1;
        }

        // ---- P @ V (3-term hi/lo) ----
#pragma unroll
        for (int np = 0; np < 4; np++) {
            const int vcol = np * 16 + sel16;
#pragma unroll
            for (int kc = 0; kc < 4; kc++) {
                const int vrow = kc * 16 + lr + sel8;
                uint32_t vd = stg + (uint32_t)(vrow * KVPITCH + vcol * 2);
                uint32_t vh[4], vl[4];
                ldsm4t(vh, vd + AVH);
                ldsm4t(vl, vd + AVL);
                mma16816(o[2*np],   pah[kc], vh[0], vh[1]);
                mma16816(o[2*np],   pah[kc], vl[0], vl[1]);
                mma16816(o[2*np],   pal[kc], vh[0], vh[1]);
                mma16816(o[2*np+1], pah[kc], vh[2], vh[3]);
                mma16816(o[2*np+1], pah[kc], vl[2], vl[3]);
                mma16816(o[2*np+1], pal[kc], vh[2], vh[3]);
            }
        }

        CPW();
        __syncthreads();
    }

    // ---- normalize + write y bf16 hi/lo ----
    const float inv0 = 1.0f / lval0;
    const float inv1 = 1.0f / lval1;
    const int row0 = bb * Sq + qt * 64 + w * 16 + crow;
#pragma unroll
    for (int j = 0; j < 8; j++) {
        const int col = hh * Dd + j * 8 + ct;
        float v00 = o[j][0] * inv0, v01 = o[j][1] * inv0;
        float v10 = o[j][2] * inv1, v11 = o[j][3] * inv1;
        __nv_bfloat16 h00 = __float2bfloat16(v00);
        __nv_bfloat16 h01 = __float2bfloat16(v01);
        __nv_bfloat16 h10 = __float2bfloat16(v10);
        __nv_bfloat16 h11 = __float2bfloat16(v11);
        __nv_bfloat162 hp0 = __nv_bfloat162(h00, h01);
        __nv_bfloat162 hp1 = __nv_bfloat162(h10, h11);
        __nv_bfloat162 lp0 = __nv_bfloat162(
            __float2bfloat16(v00 - __bfloat162float(h00)),
            __float2bfloat16(v01 - __bfloat162float(h01)));
        __nv_bfloat162 lp1 = __nv_bfloat162(
            __float2bfloat16(v10 - __bfloat162float(h10)),
            __float2bfloat16(v11 - __bfloat162float(h11)));
        size_t off0 = (size_t)row0 * Fd + col;
        size_t off1 = off0 + 8 * (size_t)Fd;
        *reinterpret_cast<uint32_t*>(&g_yhi[off0]) = *reinterpret_cast<uint32_t*>(&hp0);
        *reinterpret_cast<uint32_t*>(&g_yhi[off1]) = *reinterpret_cast<uint32_t*>(&hp1);
        *reinterpret_cast<uint32_t*>(&g_ylo[off0]) = *reinterpret_cast<uint32_t*>(&lp0);
        *reinterpret_cast<uint32_t*>(&g_ylo[off1]) = *reinterpret_cast<uint32_t*>(&lp1);
    }
}

// ---------------------------------------------------------------------------
extern "C" void kernel_launch(void* const* d_in, const int* in_sizes, int n_in,
                              void* d_out, int out_size)
{
    const float* inputs_q = (const float*)d_in[0];
    const float* Wq = (const float*)d_in[1];
    const float* bq = (const float*)d_in[2];
    const float* Wk = (const float*)d_in[3];
    const float* bk = (const float*)d_in[4];
    const float* Wv = (const float*)d_in[5];
    const float* bv = (const float*)d_in[6];
    const float* R  = (const float*)d_in[7];
    const float* Wo = (const float*)d_in[8];
    const float* bo = (const float*)d_in[9];
    float* out = (float*)d_out;

    cudaFuncSetAttribute(qkv_gemm, cudaFuncAttributeMaxDynamicSharedMemorySize, GSMEM);
    cudaFuncSetAttribute(out_gemm, cudaFuncAttributeMaxDynamicSharedMemorySize, GSMEM);
    cudaFuncSetAttribute(attn_mma, cudaFuncAttributeMaxDynamicSharedMemorySize, ASMEM);

    split_x<<<4096, 256>>>(inputs_q);
    split_wt<<<dim3(32, 32, 4), dim3(32, 8)>>>(Wq, Wk, Wv, Wo);

    qkv_gemm<<<dim3(Fd / 128, (Bsz * Sq) / 128, 3), 256, GSMEM>>>(bq, bk, bv);

    attn_mma<<<dim3(Bsz, Hh * 16), 128, ASMEM>>>(R);

    out_gemm<<<dim3(Fd / 128, (Bsz * Sq) / 128), 256, GSMEM>>>(bo, out);
}

// round 5
// speedup vs baseline: 3.0546x; 1.1828x over previous
#include <cuda_runtime.h>
#include <cuda_bf16.h>
#include <math.h>
#include <stdint.h>

#define Bsz 4
#define Sq  1024
#define Fd  1024
#define Hh  16
#define Dd  64

// ---------------------------------------------------------------------------
// Scratch (device globals)
// ---------------------------------------------------------------------------
__device__ __nv_bfloat16 g_xhi[Bsz*Sq*Fd];
__device__ __nv_bfloat16 g_xlo[Bsz*Sq*Fd];
__device__ __nv_bfloat16 g_wthi[4*Fd*Fd];   // [N][K] x4 (Wq,Wk,Wv,Wo)
__device__ __nv_bfloat16 g_wtlo[4*Fd*Fd];
// Q/K/V bf16 hi/lo in [B*H][S][D]
__device__ __nv_bfloat16 g_qh[Bsz*Hh*Sq*Dd];
__device__ __nv_bfloat16 g_ql[Bsz*Hh*Sq*Dd];
__device__ __nv_bfloat16 g_kh[Bsz*Hh*Sq*Dd];
__device__ __nv_bfloat16 g_kl[Bsz*Hh*Sq*Dd];
__device__ __nv_bfloat16 g_vh[Bsz*Hh*Sq*Dd];
__device__ __nv_bfloat16 g_vl[Bsz*Hh*Sq*Dd];
// Attention output bf16 hi/lo, [B*S][F]
__device__ __nv_bfloat16 g_yhi[Bsz*Sq*Fd];
__device__ __nv_bfloat16 g_ylo[Bsz*Sq*Fd];
// R table in bf16 (precision ample: adds ~4e-5 abs error to scores)
__device__ __nv_bfloat16 g_rb[Hh*Sq*Sq];

// ---------------------------------------------------------------------------
// PTX helpers (baseline PTX only)
// ---------------------------------------------------------------------------
__device__ __forceinline__ uint32_t smem_u32(const void* p) {
    uint32_t a;
    asm("{ .reg .u64 t; cvta.to.shared.u64 t, %1; cvt.u32.u64 %0, t; }"
        : "=r"(a) : "l"(p));
    return a;
}

#define CPA(dst, src) do {                                                   \
    uint64_t _g = __cvta_generic_to_global((const void*)(src));              \
    asm volatile("cp.async.ca.shared.global [%0], [%1], 16;"                 \
                 :: "r"(dst), "l"(_g) : "memory");                           \
} while (0)
#define CPC() asm volatile("cp.async.commit_group;" ::: "memory")
#define CPW() asm volatile("cp.async.wait_group 0;" ::: "memory")

__device__ __forceinline__ void ldsm4(uint32_t r[4], uint32_t addr) {
    asm volatile("ldmatrix.sync.aligned.m8n8.x4.shared.b16 {%0,%1,%2,%3}, [%4];"
        : "=r"(r[0]), "=r"(r[1]), "=r"(r[2]), "=r"(r[3]) : "r"(addr));
}
__device__ __forceinline__ void ldsm4t(uint32_t r[4], uint32_t addr) {
    asm volatile("ldmatrix.sync.aligned.m8n8.x4.trans.shared.b16 {%0,%1,%2,%3}, [%4];"
        : "=r"(r[0]), "=r"(r[1]), "=r"(r[2]), "=r"(r[3]) : "r"(addr));
}

__device__ __forceinline__ void mma16816(float* c, const uint32_t* a,
                                         uint32_t b0, uint32_t b1) {
    asm volatile("mma.sync.aligned.m16n8k16.row.col.f32.bf16.bf16.f32 "
        "{%0,%1,%2,%3}, {%4,%5,%6,%7}, {%8,%9}, {%0,%1,%2,%3};"
        : "+f"(c[0]), "+f"(c[1]), "+f"(c[2]), "+f"(c[3])
        : "r"(a[0]), "r"(a[1]), "r"(a[2]), "r"(a[3]), "r"(b0), "r"(b1));
}

// ---------------------------------------------------------------------------
// Conversions
// ---------------------------------------------------------------------------
__global__ void split_x(const float* __restrict__ X) {
    int i = (blockIdx.x * blockDim.x + threadIdx.x) * 4;
    float4 v = *reinterpret_cast<const float4*>(&X[i]);
    float vv[4] = {v.x, v.y, v.z, v.w};
#pragma unroll
    for (int j = 0; j < 4; j++) {
        __nv_bfloat16 h = __float2bfloat16(vv[j]);
        g_xhi[i + j] = h;
        g_xlo[i + j] = __float2bfloat16(vv[j] - __bfloat162float(h));
    }
}

__global__ void conv_r(const float* __restrict__ R) {
    int i = (blockIdx.x * blockDim.x + threadIdx.x) * 4;
    float4 v = *reinterpret_cast<const float4*>(&R[i]);
    __nv_bfloat162 p0 = __nv_bfloat162(__float2bfloat16(v.x), __float2bfloat16(v.y));
    __nv_bfloat162 p1 = __nv_bfloat162(__float2bfloat16(v.z), __float2bfloat16(v.w));
    uint2 o;
    o.x = *reinterpret_cast<uint32_t*>(&p0);
    o.y = *reinterpret_cast<uint32_t*>(&p1);
    *reinterpret_cast<uint2*>(&g_rb[i]) = o;
}

__global__ void split_wt(const float* __restrict__ Wq, const float* __restrict__ Wk,
                         const float* __restrict__ Wv, const float* __restrict__ Wo) {
    __shared__ float t[32][33];
    const int z = blockIdx.z;
    const float* __restrict__ W = (z == 0) ? Wq : (z == 1) ? Wk : (z == 2) ? Wv : Wo;
    __nv_bfloat16* hi = g_wthi + (size_t)z * Fd * Fd;
    __nv_bfloat16* lo = g_wtlo + (size_t)z * Fd * Fd;

    const int tx = threadIdx.x, ty = threadIdx.y;
    const int kbase = blockIdx.y * 32, nbase = blockIdx.x * 32;
#pragma unroll
    for (int i = 0; i < 4; i++) {
        int kr = ty * 4 + i;
        t[kr][tx] = W[(size_t)(kbase + kr) * Fd + nbase + tx];
    }
    __syncthreads();
#pragma unroll
    for (int i = 0; i < 4; i++) {
        int nr = ty * 4 + i;
        float v = t[tx][nr];
        __nv_bfloat16 h = __float2bfloat16(v);
        size_t o = (size_t)(nbase + nr) * Fd + kbase + tx;
        hi[o] = h;
        lo[o] = __float2bfloat16(v - __bfloat162float(h));
    }
}

// ---------------------------------------------------------------------------
// mma.sync GEMM (R4 core + forced 2 CTAs/SM).
// ---------------------------------------------------------------------------
#define GSMEM 81920

template<int MODE>
__device__ __forceinline__ void gemm_mma(
    const __nv_bfloat16* __restrict__ Ahi, const __nv_bfloat16* __restrict__ Alo,
    const __nv_bfloat16* __restrict__ Bhi, const __nv_bfloat16* __restrict__ Blo,
    const float* __restrict__ bias, float scale,
    float* __restrict__ C, __nv_bfloat16* __restrict__ Chi,
    __nv_bfloat16* __restrict__ Clo,
    int m0, int n0)
{
    extern __shared__ __align__(128) char smem[];
    const uint32_t sb = smem_u32(smem);
    const int tid = threadIdx.x;
    const int lane = tid & 31, wid = tid >> 5;
    const int wm = (wid >> 2) * 64;
    const int wn = (wid & 3) * 32;

    float c[4][4][4];
#pragma unroll
    for (int i = 0; i < 4; i++)
#pragma unroll
        for (int j = 0; j < 4; j++)
#pragma unroll
            for (int r = 0; r < 4; r++) c[i][j][r] = 0.0f;

    const char* pAhi = (const char*)Ahi;
    const char* pAlo = (const char*)Alo;
    const char* pBhi = (const char*)Bhi;
    const char* pBlo = (const char*)Blo;

    auto load_stage = [&](int stg, int it) {
        const int k0 = it * 32;
        const uint32_t sbase = sb + stg * 40960;
#pragma unroll
        for (int t = 0; t < 2; t++) {
            int idx = tid + t * 256;
            int row = idx >> 2;
            int cc  = (idx & 3) * 8;
            uint32_t so = sbase + row * 80 + cc * 2;
            size_t goA = ((size_t)(m0 + row) * Fd + k0 + cc) * 2;
            size_t goB = ((size_t)(n0 + row) * Fd + k0 + cc) * 2;
            CPA(so +     0, pAhi + goA);
            CPA(so + 10240, pAlo + goA);
            CPA(so + 20480, pBhi + goB);
            CPA(so + 30720, pBlo + goB);
        }
        CPC();
    };

    const int g = lane >> 3, r8 = lane & 7;

    auto compute = [&](int stg) {
        const uint32_t abase = sb + stg * 40960;
        const uint32_t bbase = abase + 20480;
#pragma unroll
        for (int ks = 0; ks < 2; ks++) {
            uint32_t ah[16], al[16];
            const int arow = (g & 1) * 8 + r8;
            const int acol = ks * 16 + (g >> 1) * 8;
#pragma unroll
            for (int mi = 0; mi < 4; mi++) {
                uint32_t ad = abase + (uint32_t)((wm + mi * 16 + arow) * 80 + acol * 2);
                ldsm4(&ah[mi * 4], ad);
                ldsm4(&al[mi * 4], ad + 10240);
            }
#pragma unroll
            for (int j2 = 0; j2 < 2; j2++) {
                uint32_t bh[4], bl[4];
                const int brow = (2 * j2 + (g >> 1)) * 8 + r8;
                const int bcol = ks * 16 + (g & 1) * 8;
                uint32_t bd = bbase + (uint32_t)((wn + brow) * 80 + bcol * 2);
                ldsm4(bh, bd);
                ldsm4(bl, bd + 10240);
#pragma unroll
                for (int mi = 0; mi < 4; mi++) {
#pragma unroll
                    for (int jj = 0; jj < 2; jj++) {
                        const int nj = 2 * j2 + jj;
                        mma16816(c[mi][nj], &ah[mi * 4], bh[jj * 2], bh[jj * 2 + 1]);
                        mma16816(c[mi][nj], &ah[mi * 4], bl[jj * 2], bl[jj * 2 + 1]);
                        mma16816(c[mi][nj], &al[mi * 4], bh[jj * 2], bh[jj * 2 + 1]);
                    }
                }
            }
        }
    };

    load_stage(0, 0);
    CPW();
    __syncthreads();
    for (int it = 0; it < Fd / 32; it++) {
        if (it + 1 < Fd / 32) load_stage((it + 1) & 1, it + 1);
        compute(it & 1);
        if (it + 1 < Fd / 32) CPW();
        __syncthreads();
    }

    const int crow = lane >> 2;
    const int ccol = (lane & 3) * 2;
#pragma unroll
    for (int mi = 0; mi < 4; mi++) {
#pragma unroll
        for (int nj = 0; nj < 4; nj++) {
            const int m = m0 + wm + mi * 16 + crow;
            const int n = n0 + wn + nj * 8 + ccol;
            const float b0 = __ldg(&bias[n]);
            const float b1 = __ldg(&bias[n + 1]);
            float v00 = (c[mi][nj][0] + b0) * scale;
            float v01 = (c[mi][nj][1] + b1) * scale;
            float v10 = (c[mi][nj][2] + b0) * scale;
            float v11 = (c[mi][nj][3] + b1) * scale;
            if (MODE == 0) {
                float2 o0 = {v00, v01}, o1 = {v10, v11};
                *reinterpret_cast<float2*>(&C[(size_t)m * Fd + n]) = o0;
                *reinterpret_cast<float2*>(&C[(size_t)(m + 8) * Fd + n]) = o1;
            } else {
                const int bb = m >> 10, ss = m & 1023;
                const int hh = n >> 6, dd = n & 63;
                size_t off0 = (((size_t)(bb * Hh + hh)) * Sq + ss) * Dd + dd;
                size_t off1 = off0 + 8 * Dd;
                __nv_bfloat16 h00 = __float2bfloat16(v00);
                __nv_bfloat16 h01 = __float2bfloat16(v01);
                __nv_bfloat16 h10 = __float2bfloat16(v10);
                __nv_bfloat16 h11 = __float2bfloat16(v11);
                __nv_bfloat162 hp0 = __nv_bfloat162(h00, h01);
                __nv_bfloat162 hp1 = __nv_bfloat162(h10, h11);
                __nv_bfloat162 lp0 = __nv_bfloat162(
                    __float2bfloat16(v00 - __bfloat162float(h00)),
                    __float2bfloat16(v01 - __bfloat162float(h01)));
                __nv_bfloat162 lp1 = __nv_bfloat162(
                    __float2bfloat16(v10 - __bfloat162float(h10)),
                    __float2bfloat16(v11 - __bfloat162float(h11)));
                *reinterpret_cast<uint32_t*>(&Chi[off0]) = *reinterpret_cast<uint32_t*>(&hp0);
                *reinterpret_cast<uint32_t*>(&Chi[off1]) = *reinterpret_cast<uint32_t*>(&hp1);
                *reinterpret_cast<uint32_t*>(&Clo[off0]) = *reinterpret_cast<uint32_t*>(&lp0);
                *reinterpret_cast<uint32_t*>(&Clo[off1]) = *reinterpret_cast<uint32_t*>(&lp1);
            }
        }
    }
}

__global__ __launch_bounds__(256, 2) void qkv_gemm(
    const float* __restrict__ bq, const float* __restrict__ bk,
    const float* __restrict__ bv)
{
    const int z = blockIdx.z;
    const float* bias = (z == 0) ? bq : (z == 1) ? bk : bv;
    __nv_bfloat16* Chi = (z == 0) ? g_qh : (z == 1) ? g_kh : g_vh;
    __nv_bfloat16* Clo = (z == 0) ? g_ql : (z == 1) ? g_kl : g_vl;
    const float scale = (z == 0) ? 0.125f : 1.0f;
    gemm_mma<1>(g_xhi, g_xlo,
                g_wthi + (size_t)z * Fd * Fd, g_wtlo + (size_t)z * Fd * Fd,
                bias, scale, nullptr, Chi, Clo,
                blockIdx.y * 128, blockIdx.x * 128);
}

__global__ __launch_bounds__(256, 2) void out_gemm(
    const float* __restrict__ bo, float* __restrict__ out)
{
    gemm_mma<0>(g_yhi, g_ylo,
                g_wthi + (size_t)3 * Fd * Fd, g_wtlo + (size_t)3 * Fd * Fd,
                bo, 1.0f, out, nullptr, nullptr,
                blockIdx.y * 128, blockIdx.x * 128);
}

// ---------------------------------------------------------------------------
// Flash attention: 64 q-rows/CTA, 32-key tiles, bf16 R, 4 CTAs/SM target.
// smem/stage: KH 4608 | KL 4608 | VH 4608 | VL 4608 | R(bf16) 5120 = 23552
// ---------------------------------------------------------------------------
#define AKH 0
#define AKL 4608
#define AVH 9216
#define AVL 13824
#define ARR 18432
#define ASTG 23552
#define ASMEM (2*ASTG)
#define KVPITCH 144
#define RPITCH 80
#define NKT 32

__global__ __launch_bounds__(128, 4) void attn_mma(const float* __restrict__ Rfp)
{
    extern __shared__ __align__(128) char smem[];
    const uint32_t sb = smem_u32(smem);
    const int tid = threadIdx.x;
    const int lane = tid & 31, w = tid >> 5;
    const int bb = blockIdx.x;
    const int hh = blockIdx.y >> 4;
    const int qt = blockIdx.y & 15;
    const int bh = bb * Hh + hh;

    const int lr = lane & 7;
    const int sel8  = (lane & 8) ? 8 : 0;
    const int sel16 = (lane & 16) ? 8 : 0;
    const int crow = lane >> 2;
    const int ct = (lane & 3) * 2;

    const __nv_bfloat16* Kh = g_kh + (size_t)bh * Sq * Dd;
    const __nv_bfloat16* Kl = g_kl + (size_t)bh * Sq * Dd;
    const __nv_bfloat16* Vh = g_vh + (size_t)bh * Sq * Dd;
    const __nv_bfloat16* Vl = g_vl + (size_t)bh * Sq * Dd;
    const __nv_bfloat16* Rp = g_rb + (size_t)hh * Sq * Sq + (size_t)(qt * 64) * Sq;

    auto load_stage = [&](int stg, int kt) {
        const int k0 = kt * 32;
        const uint32_t sbase = sb + stg * ASTG;
        // K/V hi/lo: 32 rows x 128B each
#pragma unroll
        for (int i = 0; i < 2; i++) {
            int idx = tid + i * 128;          // 0..255
            int row = idx >> 3;
            int seg = (idx & 7) * 16;
            uint32_t so = sbase + row * KVPITCH + seg;
            size_t go = ((size_t)(k0 + row)) * Dd + (seg >> 1);
            CPA(so + AKH, Kh + go);
            CPA(so + AKL, Kl + go);
            CPA(so + AVH, Vh + go);
            CPA(so + AVL, Vl + go);
        }
        // R bf16: 64 q-rows x 64B
#pragma unroll
        for (int i = 0; i < 2; i++) {
            int idx = tid + i * 128;          // 0..255
            int row = idx >> 2;
            int seg = (idx & 3) * 16;
            CPA(sbase + ARR + row * RPITCH + seg,
                Rp + (size_t)row * Sq + k0 + (seg >> 1));
        }
        CPC();
    };

    // ---- stage 0 prefetch + Q staging in stage-1 area ----
    load_stage(0, 0);
    {
        const uint32_t qbase = sb + ASTG;    // Qh at +0 (9216B), Ql at +9216
        const __nv_bfloat16* Qh = g_qh + ((size_t)bh * Sq + qt * 64) * Dd;
        const __nv_bfloat16* Ql = g_ql + ((size_t)bh * Sq + qt * 64) * Dd;
#pragma unroll
        for (int i = 0; i < 4; i++) {
            int idx = tid + i * 128;          // 0..511
            int row = idx >> 3;
            int seg = (idx & 7) * 16;
            uint32_t so = qbase + row * KVPITCH + seg;
            size_t go = (size_t)row * Dd + (seg >> 1);
            CPA(so, Qh + go);
            CPA(so + 9216, Ql + go);
        }
        CPC();
    }
    CPW();
    __syncthreads();

    uint32_t qfh[4][4], qfl[4][4];
    {
        const uint32_t qbase = sb + ASTG;
        const int arow = w * 16 + lr + sel8;
#pragma unroll
        for (int cc = 0; cc < 4; cc++) {
            const int acol = cc * 16 + sel16;
            uint32_t ad = qbase + (uint32_t)(arow * KVPITCH + acol * 2);
            ldsm4(qfh[cc], ad);
            ldsm4(qfl[cc], ad + 9216);
        }
    }
    __syncthreads();

    float o[8][4];
#pragma unroll
    for (int j = 0; j < 8; j++)
#pragma unroll
        for (int r = 0; r < 4; r++) o[j][r] = 0.0f;
    float mval0 = -1e30f, mval1 = -1e30f, lval0 = 0.0f, lval1 = 0.0f;

    for (int kt = 0; kt < NKT; kt++) {
        if (kt + 1 < NKT) load_stage((kt + 1) & 1, kt + 1);
        const uint32_t stg = sb + (kt & 1) * ASTG;

        // ---- QK^T (3-term hi/lo): 16 q-rows x 32 keys per warp ----
        float c[4][4];
#pragma unroll
        for (int j = 0; j < 4; j++)
#pragma unroll
            for (int r = 0; r < 4; r++) c[j][r] = 0.0f;

#pragma unroll
        for (int np = 0; np < 2; np++) {
            const int brow = np * 16 + lr + sel16;
#pragma unroll
            for (int cc = 0; cc < 4; cc++) {
                const int bcol = cc * 16 + sel8;
                uint32_t kd = stg + (uint32_t)(brow * KVPITCH + bcol * 2);
                uint32_t kh[4], kl[4];
                ldsm4(kh, kd + AKH);
                ldsm4(kl, kd + AKL);
                mma16816(c[2*np],   qfh[cc], kh[0], kh[1]);
                mma16816(c[2*np],   qfh[cc], kl[0], kl[1]);
                mma16816(c[2*np],   qfl[cc], kh[0], kh[1]);
                mma16816(c[2*np+1], qfh[cc], kh[2], kh[3]);
                mma16816(c[2*np+1], qfh[cc], kl[2], kl[3]);
                mma16816(c[2*np+1], qfl[cc], kh[2], kh[3]);
            }
        }

        // ---- add R (bf16), row max ----
        const char* rbase = smem + (kt & 1) * ASTG + ARR;
        const int rrow0 = w * 16 + crow;
        float mx0 = -1e30f, mx1 = -1e30f;
#pragma unroll
        for (int j = 0; j < 4; j++) {
            const int cj = j * 8 + ct;
            uint32_t u0 = *reinterpret_cast<const uint32_t*>(rbase + rrow0 * RPITCH + cj * 2);
            uint32_t u1 = *reinterpret_cast<const uint32_t*>(rbase + (rrow0 + 8) * RPITCH + cj * 2);
            float2 r0 = __bfloat1622float2(*reinterpret_cast<__nv_bfloat162*>(&u0));
            float2 r1 = __bfloat1622float2(*reinterpret_cast<__nv_bfloat162*>(&u1));
            c[j][0] += r0.x; c[j][1] += r0.y;
            c[j][2] += r1.x; c[j][3] += r1.y;
            mx0 = fmaxf(mx0, fmaxf(c[j][0], c[j][1]));
            mx1 = fmaxf(mx1, fmaxf(c[j][2], c[j][3]));
        }
        mx0 = fmaxf(mx0, __shfl_xor_sync(0xffffffffu, mx0, 1));
        mx0 = fmaxf(mx0, __shfl_xor_sync(0xffffffffu, mx0, 2));
        mx1 = fmaxf(mx1, __shfl_xor_sync(0xffffffffu, mx1, 1));
        mx1 = fmaxf(mx1, __shfl_xor_sync(0xffffffffu, mx1, 2));

        const float mn0 = fmaxf(mval0, mx0);
        const float mn1 = fmaxf(mval1, mx1);
        const float sc0 = __expf(mval0 - mn0);
        const float sc1 = __expf(mval1 - mn1);
        mval0 = mn0; mval1 = mn1;

        // ---- exp + split P into hi/lo A-fragments ----
        uint32_t pah[2][4], pal[2][4];
        float ls0 = 0.0f, ls1 = 0.0f;
#pragma unroll
        for (int j = 0; j < 4; j++) {
            float p00 = __expf(c[j][0] - mn0);
            float p01 = __expf(c[j][1] - mn0);
            float p10 = __expf(c[j][2] - mn1);
            float p11 = __expf(c[j][3] - mn1);
            ls0 += p00 + p01; ls1 += p10 + p11;
            __nv_bfloat16 h00 = __float2bfloat16(p00);
            __nv_bfloat16 h01 = __float2bfloat16(p01);
            __nv_bfloat16 h10 = __float2bfloat16(p10);
            __nv_bfloat16 h11 = __float2bfloat16(p11);
            const int kc = j >> 1, sl = (j & 1) * 2;
            {
                __nv_bfloat162 t0 = __nv_bfloat162(h00, h01);
                __nv_bfloat162 t1 = __nv_bfloat162(h10, h11);
                pah[kc][sl]   = *reinterpret_cast<uint32_t*>(&t0);
                pah[kc][sl+1] = *reinterpret_cast<uint32_t*>(&t1);
            }
            {
                __nv_bfloat162 t0 = __nv_bfloat162(
                    __float2bfloat16(p00 - __bfloat162float(h00)),
                    __float2bfloat16(p01 - __bfloat162float(h01)));
                __nv_bfloat162 t1 = __nv_bfloat162(
                    __float2bfloat16(p10 - __bfloat162float(h10)),
                    __float2bfloat16(p11 - __bfloat162float(h11)));
                pal[kc][sl]   = *reinterpret_cast<uint32_t*>(&t0);
                pal[kc][sl+1] = *reinterpret_cast<uint32_t*>(&t1);
            }
        }
        ls0 += __shfl_xor_sync(0xffffffffu, ls0, 1);
        ls0 += __shfl_xor_sync(0xffffffffu, ls0, 2);
        ls1 += __shfl_xor_sync(0xffffffffu, ls1, 1);
        ls1 += __shfl_xor_sync(0xffffffffu, ls1, 2);
        lval0 = lval0 * sc0 + ls0;
        lval1 = lval1 * sc1 + ls1;

        // ---- rescale O ----
#pragma unroll
        for (int j = 0; j < 8; j++) {
            o[j][0] *= sc0; o[j][1] *= sc0;
            o[j][2] *= sc1; o[j][3] *= sc1;
        }

        // ---- P @ V (3-term hi/lo) ----
#pragma unroll
        for (int np = 0; np < 4; np++) {
            const int vcol = np * 16 + sel16;
#pragma unroll
            for (int kc = 0; kc < 2; kc++) {
                const int vrow = kc * 16 + lr + sel8;
                uint32_t vd = stg + (uint32_t)(vrow * KVPITCH + vcol * 2);
                uint32_t vh[4], vl[4];
                ldsm4t(vh, vd + AVH);
                ldsm4t(vl, vd + AVL);
                mma16816(o[2*np],   pah[kc], vh[0], vh[1]);
                mma16816(o[2*np],   pah[kc], vl[0], vl[1]);
                mma16816(o[2*np],   pal[kc], vh[0], vh[1]);
                mma16816(o[2*np+1], pah[kc], vh[2], vh[3]);
                mma16816(o[2*np+1], pah[kc], vl[2], vl[3]);
                mma16816(o[2*np+1], pal[kc], vh[2], vh[3]);
            }
        }

        CPW();
        __syncthreads();
    }

    // ---- normalize + write y bf16 hi/lo ----
    const float inv0 = 1.0f / lval0;
    const float inv1 = 1.0f / lval1;
    const int row0 = bb * Sq + qt * 64 + w * 16 + crow;
#pragma unroll
    for (int j = 0; j < 8; j++) {
        const int col = hh * Dd + j * 8 + ct;
        float v00 = o[j][0] * inv0, v01 = o[j][1] * inv0;
        float v10 = o[j][2] * inv1, v11 = o[j][3] * inv1;
        __nv_bfloat16 h00 = __float2bfloat16(v00);
        __nv_bfloat16 h01 = __float2bfloat16(v01);
        __nv_bfloat16 h10 = __float2bfloat16(v10);
        __nv_bfloat16 h11 = __float2bfloat16(v11);
        __nv_bfloat162 hp0 = __nv_bfloat162(h00, h01);
        __nv_bfloat162 hp1 = __nv_bfloat162(h10, h11);
        __nv_bfloat162 lp0 = __nv_bfloat162(
            __float2bfloat16(v00 - __bfloat162float(h00)),
            __float2bfloat16(v01 - __bfloat162float(h01)));
        __nv_bfloat162 lp1 = __nv_bfloat162(
            __float2bfloat16(v10 - __bfloat162float(h10)),
            __float2bfloat16(v11 - __bfloat162float(h11)));
        size_t off0 = (size_t)row0 * Fd + col;
        size_t off1 = off0 + 8 * (size_t)Fd;
        *reinterpret_cast<uint32_t*>(&g_yhi[off0]) = *reinterpret_cast<uint32_t*>(&hp0);
        *reinterpret_cast<uint32_t*>(&g_yhi[off1]) = *reinterpret_cast<uint32_t*>(&hp1);
        *reinterpret_cast<uint32_t*>(&g_ylo[off0]) = *reinterpret_cast<uint32_t*>(&lp0);
        *reinterpret_cast<uint32_t*>(&g_ylo[off1]) = *reinterpret_cast<uint32_t*>(&lp1);
    }
}

// ---------------------------------------------------------------------------
extern "C" void kernel_launch(void* const* d_in, const int* in_sizes, int n_in,
                              void* d_out, int out_size)
{
    const float* inputs_q = (const float*)d_in[0];
    const float* Wq = (const float*)d_in[1];
    const float* bq = (const float*)d_in[2];
    const float* Wk = (const float*)d_in[3];
    const float* bk = (const float*)d_in[4];
    const float* Wv = (const float*)d_in[5];
    const float* bv = (const float*)d_in[6];
    const float* R  = (const float*)d_in[7];
    const float* Wo = (const float*)d_in[8];
    const float* bo = (const float*)d_in[9];
    float* out = (float*)d_out;

    cudaFuncSetAttribute(qkv_gemm, cudaFuncAttributeMaxDynamicSharedMemorySize, GSMEM);
    cudaFuncSetAttribute(out_gemm, cudaFuncAttributeMaxDynamicSharedMemorySize, GSMEM);
    cudaFuncSetAttribute(attn_mma, cudaFuncAttributeMaxDynamicSharedMemorySize, ASMEM);

    split_x<<<4096, 256>>>(inputs_q);
    split_wt<<<dim3(32, 32, 4), dim3(32, 8)>>>(Wq, Wk, Wv, Wo);
    conv_r<<<Hh * Sq * Sq / 1024, 256>>>(R);

    qkv_gemm<<<dim3(Fd / 128, (Bsz * Sq) / 128, 3), 256, GSMEM>>>(bq, bk, bv);

    attn_mma<<<dim3(Bsz, Hh * 16), 128, ASMEM>>>(R);

    out_gemm<<<dim3(Fd / 128, (Bsz * Sq) / 128), 256, GSMEM>>>(bo, out);
}